// round 2
// baseline (speedup 1.0000x reference)
#include <cuda_runtime.h>
#include <cstdint>

// Scatter-add message passing: out[dst] += x[src]
// x: [N, 64] fp32; edge_index: [2, E], dtype int32 OR int64 (JAX x64-config
// dependent) -- detected on-device.
// Mapping: 16 threads per edge; lane c owns float4 chunk c of the 64-float
// row. Half-warp per edge -> coalesced 256B row read + coalesced v4 REDs.

__device__ int g_idx_is64;

// Detect index dtype: int64 layout => hi word of each value is 0 (values are
// nonnegative < 50000). int32 layout => odd int32 slots are uniform values.
__global__ void detect_idx_kernel(const int* __restrict__ ei_raw) {
    int all_hi_zero = 1;
    #pragma unroll
    for (int i = 0; i < 64; i++) {
        if (ei_raw[2 * i + 1] != 0) { all_hi_zero = 0; break; }
    }
    g_idx_is64 = all_hi_zero;
}

__global__ void mp_scatter_kernel(const float* __restrict__ x,
                                  const void* __restrict__ ei_raw,
                                  float* __restrict__ out,
                                  int E) {
    int tid = blockIdx.x * blockDim.x + threadIdx.x;
    int e = tid >> 4;          // edge id
    int c = tid & 15;          // float4 chunk within the 64-float row
    if (e >= E) return;

    int dst, src;
    if (g_idx_is64) {
        const long long* ei = (const long long*)ei_raw;
        dst = (int)__ldg(ei + e);        // row 0 = destination (segment id)
        src = (int)__ldg(ei + E + e);    // row 1 = source (gather id)
    } else {
        const int* ei = (const int*)ei_raw;
        dst = __ldg(ei + e);
        src = __ldg(ei + E + e);
    }

    const float4* xs = (const float4*)(x + (size_t)src * 64);
    float4 v = __ldg(xs + c);

    float4* op = (float4*)(out + (size_t)dst * 64) + c;
    asm volatile("red.global.add.v4.f32 [%0], {%1, %2, %3, %4};"
                 :: "l"(op), "f"(v.x), "f"(v.y), "f"(v.z), "f"(v.w)
                 : "memory");
}

extern "C" void kernel_launch(void* const* d_in, const int* in_sizes, int n_in,
                              void* d_out, int out_size) {
    const float* x = (const float*)d_in[0];
    const void* ei = d_in[1];
    float* out = (float*)d_out;

    int E = in_sizes[1] / 2;           // edge_index is [2, E]

    detect_idx_kernel<<<1, 1>>>((const int*)ei);

    // Output is poisoned; we accumulate with atomics, so zero it first.
    cudaMemsetAsync(d_out, 0, (size_t)out_size * sizeof(float), 0);

    long long total = (long long)E * 16;
    int threads = 256;
    int blocks = (int)((total + threads - 1) / threads);
    mp_scatter_kernel<<<blocks, threads>>>(x, ei, out, E);
}